// round 7
// baseline (speedup 1.0000x reference)
#include <cuda_runtime.h>

#define NS 8192
#define NH 64
#define CC 64

// Scratch (allocation-free rule: __device__ globals)
__device__ float g_X1[NS * CC];
__device__ float g_X2[NS * CC];

// ---------------------------------------------------------------------------
// Kernel 1: 2 tiles (s values) per CTA, 256 threads. All 8 float4 loads per
// thread issued up front (MLP=8). Register-resident reductions:
//   i = tid + 256k  ->  fixed h-quad h0=(tid&15)*4, c = tid>>4 + 16k.
// ---------------------------------------------------------------------------
__global__ void __launch_bounds__(256) prep_kernel(
    const float* __restrict__ Hp, const float* __restrict__ w1,
    const float* __restrict__ W2, const float* __restrict__ w3)
{
    __shared__ float t_sm[2][64];
    const int s0   = blockIdx.x * 2;
    const int tid  = threadIdx.x;
    const int lane = tid & 31;

    if (tid < 128) ((float*)t_sm)[tid] = 0.f;

    // Front-batched streaming loads for BOTH tiles (read-once: evict-first)
    const float4* base = (const float4*)(Hp + (size_t)s0 * (CC * NH));
    float4 v[2][4];
    #pragma unroll
    for (int p = 0; p < 2; p++)
        #pragma unroll
        for (int k = 0; k < 4; k++)
            v[p][k] = __ldcs(base + p * 1024 + tid + 256 * k);

    const int h0 = (tid & 15) * 4;
    const int c0 = tid >> 4;
    const float w3v0 = __ldg(w3 + h0),     w3v1 = __ldg(w3 + h0 + 1);
    const float w3v2 = __ldg(w3 + h0 + 2), w3v3 = __ldg(w3 + h0 + 3);
    float w1c[4];
    #pragma unroll
    for (int k = 0; k < 4; k++) w1c[k] = __ldg(w1 + c0 + 16 * k);

    __syncthreads();   // t_sm init visible before atomics

    #pragma unroll
    for (int p = 0; p < 2; p++) {
        float tq0 = 0.f, tq1 = 0.f, tq2 = 0.f, tq3 = 0.f;
        #pragma unroll
        for (int k = 0; k < 4; k++) {
            tq0 += v[p][k].x * w1c[k];  tq1 += v[p][k].y * w1c[k];
            tq2 += v[p][k].z * w1c[k];  tq3 += v[p][k].w * w1c[k];

            // X2[c]: dot4 with w3, reduce across the 16-lane half sharing c
            float d = v[p][k].x * w3v0 + v[p][k].y * w3v1
                    + v[p][k].z * w3v2 + v[p][k].w * w3v3;
            #pragma unroll
            for (int o = 8; o; o >>= 1) d += __shfl_xor_sync(0xffffffffu, d, o);
            if ((lane & 15) == 0)
                g_X2[(size_t)(s0 + p) * CC + c0 + 16 * k] = d;
        }
        // t[h0..h0+3]: pair-combine lanes l / l+16, spread smem atomics
        tq0 += __shfl_xor_sync(0xffffffffu, tq0, 16);
        tq1 += __shfl_xor_sync(0xffffffffu, tq1, 16);
        tq2 += __shfl_xor_sync(0xffffffffu, tq2, 16);
        tq3 += __shfl_xor_sync(0xffffffffu, tq3, 16);
        if (lane < 16) {
            atomicAdd(&t_sm[p][h0],     tq0);
            atomicAdd(&t_sm[p][h0 + 1], tq1);
            atomicAdd(&t_sm[p][h0 + 2], tq2);
            atomicAdd(&t_sm[p][h0 + 3], tq3);
        }
    }
    __syncthreads();

    // X1[c'] = sum_h t[h] * W2[c'][h] : 4 lanes per c', both tiles
    const int cp   = tid >> 2;
    const int part = tid & 3;
    const float4* w2v = (const float4*)(W2 + cp * NH + part * 16);
    float4 w[4];
    #pragma unroll
    for (int j = 0; j < 4; j++) w[j] = __ldg(&w2v[j]);

    #pragma unroll
    for (int p = 0; p < 2; p++) {
        const float* tp = &t_sm[p][part * 16];
        float acc = 0.f;
        #pragma unroll
        for (int j = 0; j < 4; j++)
            acc += w[j].x * tp[4*j] + w[j].y * tp[4*j+1]
                 + w[j].z * tp[4*j+2] + w[j].w * tp[4*j+3];
        acc += __shfl_xor_sync(0xffffffffu, acc, 1);
        acc += __shfl_xor_sync(0xffffffffu, acc, 2);
        if (part == 0) g_X1[(size_t)(s0 + p) * CC + cp] = acc;
    }
}

// ---------------------------------------------------------------------------
// Kernel 2: one CTA (256 thr) per row s — small CTAs so ~8 interleave per SM.
//  - front-batch mask loads (evict-first), zero-write the row early (streaming)
//  - compaction FUSED with V/B gather: discovering thread loads V[j],B[j] into
//    compact smem immediately (one parallel DRAM burst for all ~82 elements)
//  - phase B touches only L2-resident X2: half-warp float4 dot + shfl reduce
//  - row sum via per-warp smem atomicAdd; sparse scatter of e*inv at the end
// ---------------------------------------------------------------------------
#define MAXM 1024   // binomial(8192, 0.01): mean 82, std 9 — >100 sigma margin

__global__ void __launch_bounds__(256) row_kernel(
    const float* __restrict__ V, const float* __restrict__ B,
    const unsigned int* __restrict__ mask, float* __restrict__ out)
{
    __shared__ int   idxs[MAXM];    // 4 KB compacted column indices
    __shared__ float v_sm[MAXM];    // 4 KB gathered V values
    __shared__ float b_sm[MAXM];    // 4 KB gathered B values
    __shared__ float e_c[MAXM];     // 4 KB compacted e values
    __shared__ float x1s[64];
    __shared__ float rowsum;
    __shared__ int   cnt;

    const int s    = blockIdx.x;
    const int tid  = threadIdx.x;
    const int lane = tid & 31;
    const int wid  = tid >> 5;
    const size_t rowoff = (size_t)s * NS;

    if (tid == 0) { cnt = 0; rowsum = 1e-6f; }
    if (tid < 64) x1s[tid] = g_X1[(size_t)s * CC + tid];

    // Front-batch the mask loads (evict-first: read exactly once)
    const uint4* mv = (const uint4*)(mask + rowoff);
    uint4 u[8];
    #pragma unroll
    for (int k = 0; k < 8; k++) u[k] = __ldcs(mv + tid + k * 256);

    // Fire-and-forget streaming zero write of the output row
    float4* out4 = (float4*)(out + rowoff);
    const float4 z4 = make_float4(0.f, 0.f, 0.f, 0.f);
    #pragma unroll
    for (int k = 0; k < 8; k++) __stcs(out4 + tid + k * 256, z4);

    __syncthreads();   // cnt/rowsum/x1s visible

    // --- Phase A: compaction + fused V/B gather -----------------------------
    #pragma unroll
    for (int k = 0; k < 8; k++) {
        if (u[k].x | u[k].y | u[k].z | u[k].w) {
            int bj = (tid + k * 256) * 4;
            #pragma unroll
            for (int q = 0; q < 4; q++) {
                unsigned int bit = (q == 0) ? u[k].x : (q == 1) ? u[k].y
                                 : (q == 2) ? u[k].z : u[k].w;
                if (bit) {
                    int j = bj + q;
                    int p = atomicAdd(&cnt, 1);
                    if (p < MAXM) {
                        idxs[p] = j;
                        v_sm[p] = __ldcs(V + rowoff + j);
                        b_sm[p] = __ldcs(B + rowoff + j);
                    }
                }
            }
        }
    }
    __syncthreads();
    const int m = (cnt < MAXM) ? cnt : MAXM;

    // --- Phase B: half-warp per element (X2 from L2 only) -------------------
    const int half = lane >> 4;                       // 0 or 1
    const int hl   = lane & 15;
    const unsigned hmask = 0xFFFFu << (half * 16);
    const float4 x1v = *(const float4*)(x1s + hl * 4);
    float lsum = 0.f;

    for (int el = wid * 2 + half; el < m; el += 16) { // 16 half-warps
        const int j = idxs[el];
        const float4 xv = __ldg((const float4*)(g_X2 + (size_t)j * CC) + hl);
        float p = xv.x * x1v.x + xv.y * x1v.y + xv.z * x1v.z + xv.w * x1v.w;
        #pragma unroll
        for (int o = 8; o; o >>= 1) p += __shfl_xor_sync(hmask, p, o);
        if (hl == 0) {
            const float sg = 1.f / (1.f + expf(-(p + b_sm[el])));
            const float ev = expf(v_sm[el] * sg);
            e_c[el] = ev;
            lsum += ev;
        }
    }

    // --- Row sum: warp reduce + one smem atomic per warp --------------------
    #pragma unroll
    for (int o = 16; o; o >>= 1) lsum += __shfl_down_sync(0xffffffffu, lsum, o);
    if (lane == 0 && lsum != 0.f) atomicAdd(&rowsum, lsum);
    __syncthreads();

    // --- Sparse scatter of scaled values over the zeros ---------------------
    const float inv = 1.f / rowsum;
    for (int el = tid; el < m; el += 256)
        __stcs(out + rowoff + idxs[el], e_c[el] * inv);
}

extern "C" void kernel_launch(void* const* d_in, const int* in_sizes, int n_in,
                              void* d_out, int out_size)
{
    (void)in_sizes; (void)n_in; (void)out_size;
    const float* Hp  = (const float*)d_in[0];
    const float* w1  = (const float*)d_in[1];
    const float* W2  = (const float*)d_in[2];
    const float* w3  = (const float*)d_in[3];
    const float* V   = (const float*)d_in[4];
    const float* B   = (const float*)d_in[5];
    const unsigned int* mask = (const unsigned int*)d_in[6];
    float* out = (float*)d_out;

    prep_kernel<<<NS / 2, 256>>>(Hp, w1, W2, w3);
    row_kernel<<<NS, 256>>>(V, B, mask, out);
}

// round 8
// speedup vs baseline: 1.2804x; 1.2804x over previous
#include <cuda_runtime.h>

#define NS 8192
#define NH 64
#define CC 64

// Scratch (allocation-free rule: __device__ globals)
__device__ float g_X1[NS * CC];
__device__ float g_X2[NS * CC];

// ---------------------------------------------------------------------------
// Kernel 1: 4 tiles (s values) per CTA, 256 threads, ALL 16 float4 loads per
// thread front-batched (MLP=16 — streaming kernel, low occupancy is fine).
// Register-resident reductions: i = tid + 256k -> fixed h-quad h0=(tid&15)*4,
// c = tid>>4 + 16k.
// ---------------------------------------------------------------------------
#define TILES 4

__global__ void __launch_bounds__(256) prep_kernel(
    const float* __restrict__ Hp, const float* __restrict__ w1,
    const float* __restrict__ W2, const float* __restrict__ w3)
{
    __shared__ float t_sm[TILES][64];
    const int s0   = blockIdx.x * TILES;
    const int tid  = threadIdx.x;
    const int lane = tid & 31;

    ((float*)t_sm)[tid] = 0.f;   // 256 floats == TILES*64

    // Front-batched streaming loads for ALL tiles (read-once: evict-first)
    const float4* base = (const float4*)(Hp + (size_t)s0 * (CC * NH));
    float4 v[TILES][4];
    #pragma unroll
    for (int p = 0; p < TILES; p++)
        #pragma unroll
        for (int k = 0; k < 4; k++)
            v[p][k] = __ldcs(base + p * 1024 + tid + 256 * k);

    const int h0 = (tid & 15) * 4;
    const int c0 = tid >> 4;
    const float w3v0 = __ldg(w3 + h0),     w3v1 = __ldg(w3 + h0 + 1);
    const float w3v2 = __ldg(w3 + h0 + 2), w3v3 = __ldg(w3 + h0 + 3);
    float w1c[4];
    #pragma unroll
    for (int k = 0; k < 4; k++) w1c[k] = __ldg(w1 + c0 + 16 * k);

    __syncthreads();   // t_sm init visible before atomics

    #pragma unroll
    for (int p = 0; p < TILES; p++) {
        float tq0 = 0.f, tq1 = 0.f, tq2 = 0.f, tq3 = 0.f;
        #pragma unroll
        for (int k = 0; k < 4; k++) {
            tq0 += v[p][k].x * w1c[k];  tq1 += v[p][k].y * w1c[k];
            tq2 += v[p][k].z * w1c[k];  tq3 += v[p][k].w * w1c[k];

            // X2[c]: dot4 with w3, reduce across the 16-lane half sharing c
            float d = v[p][k].x * w3v0 + v[p][k].y * w3v1
                    + v[p][k].z * w3v2 + v[p][k].w * w3v3;
            #pragma unroll
            for (int o = 8; o; o >>= 1) d += __shfl_xor_sync(0xffffffffu, d, o);
            if ((lane & 15) == 0)
                g_X2[(size_t)(s0 + p) * CC + c0 + 16 * k] = d;
        }
        // t[h0..h0+3]: pair-combine lanes l / l+16, spread smem atomics
        tq0 += __shfl_xor_sync(0xffffffffu, tq0, 16);
        tq1 += __shfl_xor_sync(0xffffffffu, tq1, 16);
        tq2 += __shfl_xor_sync(0xffffffffu, tq2, 16);
        tq3 += __shfl_xor_sync(0xffffffffu, tq3, 16);
        if (lane < 16) {
            atomicAdd(&t_sm[p][h0],     tq0);
            atomicAdd(&t_sm[p][h0 + 1], tq1);
            atomicAdd(&t_sm[p][h0 + 2], tq2);
            atomicAdd(&t_sm[p][h0 + 3], tq3);
        }
    }
    __syncthreads();

    // X1[c'] = sum_h t[h] * W2[c'][h] : 4 lanes per c', all tiles
    const int cp   = tid >> 2;
    const int part = tid & 3;
    const float4* w2v = (const float4*)(W2 + cp * NH + part * 16);
    float4 w[4];
    #pragma unroll
    for (int j = 0; j < 4; j++) w[j] = __ldg(&w2v[j]);

    #pragma unroll
    for (int p = 0; p < TILES; p++) {
        const float* tp = &t_sm[p][part * 16];
        float acc = 0.f;
        #pragma unroll
        for (int j = 0; j < 4; j++)
            acc += w[j].x * tp[4*j] + w[j].y * tp[4*j+1]
                 + w[j].z * tp[4*j+2] + w[j].w * tp[4*j+3];
        acc += __shfl_xor_sync(0xffffffffu, acc, 1);
        acc += __shfl_xor_sync(0xffffffffu, acc, 2);
        if (part == 0) g_X1[(size_t)(s0 + p) * CC + cp] = acc;
    }
}

// ---------------------------------------------------------------------------
// Kernel 2: one CTA (512 thr) per row s — exact R6 version (129.1 us, 96% occ).
//  - front-batch mask loads (evict-first), zero-write the row early (streaming)
//  - compact masked columns, HALF-WARP per element: float4 X2 loads, 4-shfl
//  - row sum via per-warp smem atomicAdd; sparse scatter of e*inv at the end
// ---------------------------------------------------------------------------
#define MAXM 2048   // binomial(8192, 0.01): mean 82, std 9 — huge margin

__global__ void __launch_bounds__(512) row_kernel(
    const float* __restrict__ V, const float* __restrict__ B,
    const unsigned int* __restrict__ mask, float* __restrict__ out)
{
    __shared__ int   idxs[MAXM];    // 8 KB compacted column indices
    __shared__ float e_c[MAXM];     // 8 KB compacted e values
    __shared__ float x1s[64];
    __shared__ float rowsum;
    __shared__ int   cnt;

    const int s    = blockIdx.x;
    const int tid  = threadIdx.x;
    const int lane = tid & 31;
    const int wid  = tid >> 5;
    const size_t rowoff = (size_t)s * NS;

    if (tid == 0) { cnt = 0; rowsum = 1e-6f; }
    if (tid < 64) x1s[tid] = g_X1[(size_t)s * CC + tid];

    // Front-batch the mask loads (evict-first: read exactly once)
    const uint4* mv = (const uint4*)(mask + rowoff);
    uint4 u[4];
    #pragma unroll
    for (int k = 0; k < 4; k++) u[k] = __ldcs(mv + tid + k * 512);

    // Fire-and-forget streaming zero write of the output row
    float4* out4 = (float4*)(out + rowoff);
    const float4 z4 = make_float4(0.f, 0.f, 0.f, 0.f);
    #pragma unroll
    for (int k = 0; k < 4; k++) __stcs(out4 + tid + k * 512, z4);

    __syncthreads();   // cnt/rowsum/x1s visible

    // --- Phase A: compaction ----------------------------------------------
    #pragma unroll
    for (int k = 0; k < 4; k++) {
        if (u[k].x | u[k].y | u[k].z | u[k].w) {
            int bj = (tid + k * 512) * 4;
            if (u[k].x) { int p = atomicAdd(&cnt, 1); idxs[p] = bj;     }
            if (u[k].y) { int p = atomicAdd(&cnt, 1); idxs[p] = bj + 1; }
            if (u[k].z) { int p = atomicAdd(&cnt, 1); idxs[p] = bj + 2; }
            if (u[k].w) { int p = atomicAdd(&cnt, 1); idxs[p] = bj + 3; }
        }
    }
    __syncthreads();
    const int m = cnt;

    // --- Phase B: half-warp per element ------------------------------------
    const int half = lane >> 4;                       // 0 or 1
    const int hl   = lane & 15;
    const unsigned hmask = 0xFFFFu << (half * 16);
    const float4 x1v = *(const float4*)(x1s + hl * 4);
    float lsum = 0.f;

    for (int el = wid * 2 + half; el < m; el += 32) {
        const int j = idxs[el];
        const float bb = __ldg(B + rowoff + j);       // half-warp broadcast
        const float vv = __ldg(V + rowoff + j);
        const float4 xv = __ldg((const float4*)(g_X2 + (size_t)j * CC) + hl);
        float p = xv.x * x1v.x + xv.y * x1v.y + xv.z * x1v.z + xv.w * x1v.w;
        #pragma unroll
        for (int o = 8; o; o >>= 1) p += __shfl_xor_sync(hmask, p, o);
        if (hl == 0) {
            const float sg = 1.f / (1.f + expf(-(p + bb)));
            const float ev = expf(vv * sg);
            e_c[el] = ev;
            lsum += ev;
        }
    }

    // --- Row sum: warp reduce + one smem atomic per warp --------------------
    #pragma unroll
    for (int o = 16; o; o >>= 1) lsum += __shfl_down_sync(0xffffffffu, lsum, o);
    if (lane == 0 && lsum != 0.f) atomicAdd(&rowsum, lsum);
    __syncthreads();

    // --- Sparse scatter of scaled values over the zeros ---------------------
    const float inv = 1.f / rowsum;
    for (int el = tid; el < m; el += 512)
        __stcs(out + rowoff + idxs[el], e_c[el] * inv);
}

extern "C" void kernel_launch(void* const* d_in, const int* in_sizes, int n_in,
                              void* d_out, int out_size)
{
    (void)in_sizes; (void)n_in; (void)out_size;
    const float* Hp  = (const float*)d_in[0];
    const float* w1  = (const float*)d_in[1];
    const float* W2  = (const float*)d_in[2];
    const float* w3  = (const float*)d_in[3];
    const float* V   = (const float*)d_in[4];
    const float* B   = (const float*)d_in[5];
    const unsigned int* mask = (const unsigned int*)d_in[6];
    float* out = (float*)d_out;

    prep_kernel<<<NS / TILES, 256>>>(Hp, w1, W2, w3);
    row_kernel<<<NS, 512>>>(V, B, mask, out);
}